// round 15
// baseline (speedup 1.0000x reference)
#include <cuda_runtime.h>
#include <cuda_bf16.h>
#include <math.h>
#include <stdint.h>

// ---------------------------------------------------------------------------
// WindowCrossAttention  B=4096, N=64, C=256, H=8, Dh=32
// Round 15: A-resident gemm_qkv widened to 256-row m-tiles (1024 CTAs ->
// B-weight L2 traffic halved). 512 thr, 16 warps (4m x 4n), A 128KB resident,
// B 3-stage cp.async ring unchanged. attn + proj_ln R14-exact.
// ---------------------------------------------------------------------------

#define Bwin 4096
#define Hh   8
#define Mrows (Bwin * 64)              // 262144

typedef __nv_bfloat16 bf16;

// scratch (static device arrays; no allocations allowed)
__device__ bf16  g_qkv1[(size_t)Mrows * 768];
__device__ bf16  g_qkv2[(size_t)Mrows * 768];
__device__ bf16  g_o1[(size_t)Mrows * 256];
__device__ bf16  g_o2[(size_t)Mrows * 256];
__device__ bf16  g_wtq1[768 * 256];
__device__ bf16  g_wtq2[768 * 256];
__device__ bf16  g_wtp1[256 * 256];
__device__ bf16  g_wtp2[256 * 256];

__device__ __forceinline__ uint32_t pk(float lo, float hi) {
    __nv_bfloat162 t = __float22bfloat162_rn(make_float2(lo, hi));
    return *reinterpret_cast<uint32_t*>(&t);
}
__device__ __forceinline__ uint32_t smem_u32(const void* p) {
    uint32_t a;
    asm("{ .reg .u64 t; cvta.to.shared.u64 t, %1; cvt.u32.u64 %0, t; }"
        : "=r"(a) : "l"(p));
    return a;
}
__device__ __forceinline__ void mma16(float* c, uint4 a, uint2 b) {
    asm volatile(
        "mma.sync.aligned.m16n8k16.row.col.f32.bf16.bf16.f32 "
        "{%0,%1,%2,%3}, {%4,%5,%6,%7}, {%8,%9}, {%0,%1,%2,%3};"
        : "+f"(c[0]), "+f"(c[1]), "+f"(c[2]), "+f"(c[3])
        : "r"(a.x), "r"(a.y), "r"(a.z), "r"(a.w), "r"(b.x), "r"(b.y));
}
__device__ __forceinline__ uint4 ldsm_x4(uint32_t addr) {
    uint4 r;
    asm volatile("ldmatrix.sync.aligned.m8n8.x4.shared.b16 {%0,%1,%2,%3}, [%4];"
                 : "=r"(r.x), "=r"(r.y), "=r"(r.z), "=r"(r.w) : "r"(addr));
    return r;
}
__device__ __forceinline__ uint2 ldsm_x2_trans(uint32_t addr) {
    uint2 r;
    asm volatile("ldmatrix.sync.aligned.m8n8.x2.trans.shared.b16 {%0,%1}, [%2];"
                 : "=r"(r.x), "=r"(r.y) : "r"(addr));
    return r;
}
__device__ __forceinline__ void cp16_cg(uint32_t dst, const void* src) {
    asm volatile("cp.async.cg.shared.global [%0], [%1], 16;"
                 :: "r"(dst), "l"(src));
}
__device__ __forceinline__ void cp_commit() {
    asm volatile("cp.async.commit_group;" ::: "memory");
}
template <int N>
__device__ __forceinline__ void cp_wait() {
    asm volatile("cp.async.wait_group %0;" :: "n"(N) : "memory");
}

// XOR swizzle for cp.async tiles: 64B rows, phys granule = g ^ ((row>>1)&3)
#define SWZ(row, g) ((uint32_t)((row) * 64 + (((g) ^ (((row) >> 1) & 3)) * 16)))

// padded-row tiles (LDG+STS path + attention): 40 bf16 = 80B rows
#define RP 40
#define RPB 80

// ---------------------------------------------------------------------------
// Weight transposes (all four in one launch, z selects)
// ---------------------------------------------------------------------------
__global__ void transpose_all(const float* __restrict__ Wq1, bf16* __restrict__ Tq1,
                              const float* __restrict__ Wq2, bf16* __restrict__ Tq2,
                              const float* __restrict__ Wp1, bf16* __restrict__ Tp1,
                              const float* __restrict__ Wp2, bf16* __restrict__ Tp2) {
    const float* W;
    bf16* Wt;
    int Nc;
    switch (blockIdx.z) {
        case 0: W = Wq1; Wt = Tq1; Nc = 768; break;
        case 1: W = Wq2; Wt = Tq2; Nc = 768; break;
        case 2: W = Wp1; Wt = Tp1; Nc = 256; break;
        default: W = Wp2; Wt = Tp2; Nc = 256; break;
    }
    if (blockIdx.x * 32 >= Nc) return;
    __shared__ float tile[32][33];
    int n0 = blockIdx.x * 32;
    int k0 = blockIdx.y * 32;
    int tx = threadIdx.x, ty = threadIdx.y;
#pragma unroll
    for (int r = 0; r < 4; r++)
        tile[ty + 8 * r][tx] = W[(size_t)(k0 + ty + 8 * r) * Nc + n0 + tx];
    __syncthreads();
#pragma unroll
    for (int r = 0; r < 4; r++)
        Wt[(size_t)(n0 + ty + 8 * r) * 256 + k0 + tx] =
            __float2bfloat16_rn(tile[tx][ty + 8 * r]);
}

// ---------------------------------------------------------------------------
// A-resident QKV GEMM: CTA = one 256-row m-tile, ALL 6 n-tiles.
// 512 threads, 16 warps (4m x 4n), warp 64x32 per n-tile, BK=32.
// Phase 0: A (256x256 fp32) -> bf16 smem (128KB, chunk-major).
// Mainloop: 48 B-chunks streamed via cp.async 3-stage ring. grid.z = dir.
// ---------------------------------------------------------------------------
__global__ __launch_bounds__(512, 1)
void gemm_qkv(const float* __restrict__ x, const float* __restrict__ y,
              const bf16* __restrict__ wt1, const bf16* __restrict__ wt2,
              const float* __restrict__ bq1, const float* __restrict__ bq2,
              bf16* __restrict__ c1, bf16* __restrict__ c2) {
    __shared__ __align__(16) bf16 Af[8][256][32];   // 128KB, chunk-major
    __shared__ __align__(16) bf16 Bs[3][128][32];   // 24KB
    const int Nc = 768;
    const uint32_t BBYTES = 128 * 64;

    const float* A    = blockIdx.z ? y : x;
    const bf16* Bt    = blockIdx.z ? wt2 : wt1;
    const float* bias = blockIdx.z ? bq2 : bq1;
    bf16* C           = blockIdx.z ? c2 : c1;

    const int t = threadIdx.x;
    const int w = t >> 5, lane = t & 31;
    const int warp_m = w >> 2, warp_n = w & 3;   // 4m x 4n
    const int mBase = blockIdx.x * 256;

    const float* Ab = A + (size_t)mBase * 256;

    const int lr = t >> 2;          // 0..127
    const int lg = t & 3;
    const uint32_t aSm = smem_u32(&Af[0][0][0]);
    const uint32_t bSm = smem_u32(&Bs[0][0][0]);
    const uint32_t swA0 = SWZ(lr, lg);
    const uint32_t swA1 = SWZ(lr + 128, lg);

    // B chunk loader: global chunk index gi in [0,48); nt = gi>>3, c = gi&7
    // 512 threads x 16B = 8KB = one full 128x32 bf16 chunk.
    auto CPB = [&](int gi) {
        int nt = gi >> 3, c = gi & 7;
        const bf16* Bb = Bt + (size_t)(nt * 128) * 256 + c * 32;
        uint32_t dst = bSm + (uint32_t)(gi % 3) * BBYTES;
        cp16_cg(dst + SWZ(lr, lg), Bb + (size_t)lr * 256 + lg * 8);
        cp_commit();
    };

    // prefetch first two B chunks, then stage A (overlaps B DRAM fetch)
    CPB(0);
    CPB(1);
#pragma unroll 1
    for (int c = 0; c < 8; c++) {
#pragma unroll
        for (int rr = 0; rr < 2; rr++) {
            const float* p = Ab + (size_t)(lr + rr * 128) * 256 + c * 32 + lg * 8;
            float4 v0 = *(const float4*)p;
            float4 v1 = *(const float4*)(p + 4);
            uint4 pkv = { pk(v0.x, v0.y), pk(v0.z, v0.w),
                          pk(v1.x, v1.y), pk(v1.z, v1.w) };
            *(uint4*)((char*)&Af[c][0][0] + (rr ? swA1 : swA0)) = pkv;
        }
    }
    __syncthreads();   // A visible to all warps

    // ldmatrix lane addressing
    const int row0a = warp_m * 64 + (lane & 15);
    const int sela = (row0a >> 1) & 3;
    const int hia = lane >> 4;
    const uint32_t ga0 = (uint32_t)((hia ^ sela) * 16);
    const uint32_t ga1 = (uint32_t)(((2 + hia) ^ sela) * 16);
    const uint32_t aAddr = aSm + (uint32_t)row0a * 64;

    const int row0b = warp_n * 32 + (lane & 7) + ((lane >> 4) & 1) * 8;
    const int selb = (row0b >> 1) & 3;
    const int hib = (lane >> 3) & 1;
    const uint32_t gb0 = (uint32_t)((hib ^ selb) * 16);
    const uint32_t gb1 = (uint32_t)(((2 + hib) ^ selb) * 16);
    const uint32_t bAddr = bSm + (uint32_t)row0b * 64;

    const int g = lane >> 2;
    const int tq = lane & 3;

#pragma unroll 1
    for (int nt = 0; nt < 6; nt++) {
        float acc[4][4][4] = {};
#pragma unroll 1
        for (int c = 0; c < 8; c++) {
            const int gi = nt * 8 + c;
            if (gi < 47) cp_wait<1>(); else cp_wait<0>();
            __syncthreads();
            if (gi < 46) CPB(gi + 2);

            const uint32_t ab = aAddr + (uint32_t)c * 16384;   // 256 rows x 64B
            const uint32_t bb = bAddr + (uint32_t)(gi % 3) * BBYTES;
#pragma unroll
            for (int kf = 0; kf < 2; kf++) {
                const uint32_t go_a = kf ? ga1 : ga0;
                const uint32_t go_b = kf ? gb1 : gb0;
                uint4 av[4];
#pragma unroll
                for (int mf = 0; mf < 4; mf++)
                    av[mf] = ldsm_x4(ab + (uint32_t)mf * 1024 + go_a);
                uint4 bp0 = ldsm_x4(bb + go_b);
                uint4 bp1 = ldsm_x4(bb + 1024 + go_b);
                uint2 bv[4] = { {bp0.x, bp0.y}, {bp0.z, bp0.w},
                                {bp1.x, bp1.y}, {bp1.z, bp1.w} };
#pragma unroll
                for (int mf = 0; mf < 4; mf++)
#pragma unroll
                    for (int nf = 0; nf < 4; nf++)
                        mma16(acc[mf][nf], av[mf], bv[nf]);
            }
        }

        // epilogue for this n-tile: bias add + bf16 store
        const int nBase = nt * 128;
        float2 bz[4];
#pragma unroll
        for (int nf = 0; nf < 4; nf++)
            bz[nf] = *(const float2*)(bias + nBase + warp_n * 32 + nf * 8 + 2 * tq);

#pragma unroll
        for (int mf = 0; mf < 4; mf++) {
            int row0 = mBase + warp_m * 64 + mf * 16 + g;
#pragma unroll
            for (int nf = 0; nf < 4; nf++) {
                int col = nBase + warp_n * 32 + nf * 8 + 2 * tq;
                *(uint32_t*)(C + (size_t)row0 * Nc + col) =
                    pk(acc[mf][nf][0] + bz[nf].x, acc[mf][nf][1] + bz[nf].y);
                *(uint32_t*)(C + (size_t)(row0 + 8) * Nc + col) =
                    pk(acc[mf][nf][2] + bz[nf].x, acc[mf][nf][3] + bz[nf].y);
            }
        }
    }
}

// ---------------------------------------------------------------------------
// FUSED proj + bias + residual + LayerNorm (R9 exact).  CTA 128 x 256,
// 512 threads, 16 warps (2m x 8n), BK=32, LDG+STS double buffer. grid.z = dir.
// ---------------------------------------------------------------------------
__global__ __launch_bounds__(512, 1)
void proj_ln(const bf16* __restrict__ o1, const bf16* __restrict__ o2,
             const bf16* __restrict__ wt1, const bf16* __restrict__ wt2,
             const float* __restrict__ bp1, const float* __restrict__ bp2,
             const float* __restrict__ x, const float* __restrict__ y,
             const float* __restrict__ g1, const float* __restrict__ be1,
             const float* __restrict__ g2, const float* __restrict__ be2,
             float* __restrict__ outbase) {
    __shared__ __align__(16) bf16 As[2][128][RP];   // 20KB
    __shared__ __align__(16) bf16 Bs[2][256][RP];   // 40KB
    __shared__ float2 red[128][8];                  // 8KB
    __shared__ float2 mv[128];

    const bf16* A      = blockIdx.z ? o2 : o1;
    const bf16* Bt     = blockIdx.z ? wt2 : wt1;
    const float* bias  = blockIdx.z ? bp2 : bp1;
    const float* resid = blockIdx.z ? y : x;
    const float* gamma = blockIdx.z ? g2 : g1;
    const float* beta  = blockIdx.z ? be2 : be1;
    float* out = outbase + (size_t)blockIdx.z * Mrows * 256;

    const int t = threadIdx.x;
    const int w = t >> 5, lane = t & 31;
    const int warp_m = w >> 3;        // 0..1
    const int warp_n = w & 7;         // 0..7
    const int g = lane >> 2, tq = lane & 3;
    const int mBase = blockIdx.x * 128;

    const bf16* Ab = A + (size_t)mBase * 256;

    const int lr = t >> 2;            // 0..127
    const int lg = t & 3;

    uint4 ast, bst[2];
    auto LDG = [&](int kc) {
        ast = *(const uint4*)(Ab + (size_t)lr * 256 + kc + lg * 8);
#pragma unroll
        for (int rr = 0; rr < 2; rr++)
            bst[rr] = *(const uint4*)(Bt + (size_t)(lr + rr * 128) * 256 + kc + lg * 8);
    };
    auto STS = [&](int buf) {
        *(uint4*)&As[buf][lr][lg * 8] = ast;
#pragma unroll
        for (int rr = 0; rr < 2; rr++)
            *(uint4*)&Bs[buf][lr + rr * 128][lg * 8] = bst[rr];
    };

    uint32_t a_base = smem_u32(&As[0][0][0]) +
        (uint32_t)(warp_m * 64 + (lane & 15)) * RPB + (uint32_t)(lane >> 4) * 16;
    uint32_t b_base = smem_u32(&Bs[0][0][0]) +
        (uint32_t)(warp_n * 32 + (lane & 7) + ((lane >> 4) & 1) * 8) * RPB +
        (uint32_t)((lane >> 3) & 1) * 16;

    float acc[4][4][4] = {};

    LDG(0);
    STS(0);
    __syncthreads();

#pragma unroll 1
    for (int c = 0; c < 8; c++) {
        if (c < 7) LDG((c + 1) * 32);
        const uint32_t ab = a_base + (uint32_t)(c & 1) * (128 * RPB);
        const uint32_t bb = b_base + (uint32_t)(c & 1) * (256 * RPB);
#pragma unroll
        for (int kf = 0; kf < 2; kf++) {
            uint4 av[4];
#pragma unroll
            for (int mf = 0; mf < 4; mf++)
                av[mf] = ldsm_x4(ab + (uint32_t)mf * 16 * RPB + (uint32_t)kf * 32);
            uint4 bp0 = ldsm_x4(bb + (uint32_t)kf * 32);
            uint4 bp1 = ldsm_x4(bb + 16 * RPB + (uint32_t)kf * 32);
            uint2 bv[4] = { {bp0.x, bp0.y}, {bp0.z, bp0.w},
                            {bp1.x, bp1.y}, {bp1.z, bp1.w} };
#pragma unroll
            for (int mf = 0; mf < 4; mf++)
#pragma unroll
                for (int nf = 0; nf < 4; nf++)
                    mma16(acc[mf][nf], av[mf], bv[nf]);
        }
        if (c < 7) {
            STS((c + 1) & 1);
            __syncthreads();
        }
    }

    // epilogue pass 1: val = acc + bias + resid, per-row partial stats
    float2 bz[4];
#pragma unroll
    for (int nf = 0; nf < 4; nf++)
        bz[nf] = *(const float2*)(bias + warp_n * 32 + nf * 8 + 2 * tq);

#pragma unroll
    for (int mf = 0; mf < 4; mf++) {
        int r0 = warp_m * 64 + mf * 16 + g;
        float plo = 0.0f, phi = 0.0f, qlo = 0.0f, qhi = 0.0f;
#pragma unroll
        for (int nf = 0; nf < 4; nf++) {
            int col = warp_n * 32 + nf * 8 + 2 * tq;
            float2 x0 = *(const float2*)(resid + (size_t)(mBase + r0) * 256 + col);
            float2 x1 = *(const float2*)(resid + (size_t)(mBase + r0 + 8) * 256 + col);
            float v0 = acc[mf][nf][0] + bz[nf].x + x0.x;
            float v1 = acc[mf][nf][1] + bz[nf].y + x0.y;
            float v2 = acc[mf][nf][2] + bz[nf].x + x1.x;
            float v3 = acc[mf][nf][3] + bz[nf].y + x1.y;
            acc[mf][nf][0] = v0; acc[mf][nf][1] = v1;
            acc[mf][nf][2] = v2; acc[mf][nf][3] = v3;
            plo += v0 + v1; phi += v2 + v3;
            qlo += v0 * v0 + v1 * v1; qhi += v2 * v2 + v3 * v3;
        }
        plo += __shfl_xor_sync(0xffffffffu, plo, 1);
        plo += __shfl_xor_sync(0xffffffffu, plo, 2);
        qlo += __shfl_xor_sync(0xffffffffu, qlo, 1);
        qlo += __shfl_xor_sync(0xffffffffu, qlo, 2);
        phi += __shfl_xor_sync(0xffffffffu, phi, 1);
        phi += __shfl_xor_sync(0xffffffffu, phi, 2);
        qhi += __shfl_xor_sync(0xffffffffu, qhi, 1);
        qhi += __shfl_xor_sync(0xffffffffu, qhi, 2);
        if (tq == 0) {
            red[r0][warp_n]     = make_float2(plo, qlo);
            red[r0 + 8][warp_n] = make_float2(phi, qhi);
        }
    }
    __syncthreads();

    if (t < 128) {
        float s = 0.0f, q = 0.0f;
#pragma unroll
        for (int j = 0; j < 8; j++) { s += red[t][j].x; q += red[t][j].y; }
        float mean = s * (1.0f / 256.0f);
        float var = q * (1.0f / 256.0f) - mean * mean;
        mv[t] = make_float2(mean, rsqrtf(var + 1e-5f));
    }
    __syncthreads();

    // epilogue pass 2: normalize + affine + store
#pragma unroll
    for (int nf = 0; nf < 4; nf++) {
        int col = warp_n * 32 + nf * 8 + 2 * tq;
        float2 gm = *(const float2*)(gamma + col);
        float2 bt = *(const float2*)(beta + col);
#pragma unroll
        for (int mf = 0; mf < 4; mf++) {
            int r0 = warp_m * 64 + mf * 16 + g;
            float2 m0 = mv[r0];
            float2 m1 = mv[r0 + 8];
            float2 u0 = { (acc[mf][nf][0] - m0.x) * m0.y * gm.x + bt.x,
                          (acc[mf][nf][1] - m0.x) * m0.y * gm.y + bt.y };
            float2 u1 = { (acc[mf][nf][2] - m1.x) * m1.y * gm.x + bt.x,
                          (acc[mf][nf][3] - m1.x) * m1.y * gm.y + bt.y };
            *(float2*)(out + (size_t)(mBase + r0) * 256 + col) = u0;
            *(float2*)(out + (size_t)(mBase + r0 + 8) * 256 + col) = u1;
        }
    }
}

// ---------------------------------------------------------------------------
// Tensor-core attention (R9 exact): block per (b,h), 128 threads, grid.z=dir.
// ---------------------------------------------------------------------------
__global__ __launch_bounds__(128)
void attn_tc(const bf16* __restrict__ qkv1, const bf16* __restrict__ qkv2,
             const float* __restrict__ bias1, const float* __restrict__ bias2,
             bf16* __restrict__ o1, bf16* __restrict__ o2) {
    const bf16* qkvQ  = blockIdx.z ? qkv2 : qkv1;
    const bf16* qkvKV = blockIdx.z ? qkv1 : qkv2;
    const float* bias = blockIdx.z ? bias2 : bias1;
    bf16* out         = blockIdx.z ? o2 : o1;

    const int b = blockIdx.x;
    const int h = blockIdx.y;
    const int t = threadIdx.x;
    const int w = t >> 5;
    const int lane = t & 31;
    const int g = lane >> 2;
    const int tq = lane & 3;

    __shared__ __align__(16) bf16 Ks[64][RP];
    __shared__ __align__(16) bf16 Vs[64][RP];

    const bf16* base = qkvKV + (size_t)b * 64 * 768;
    {
        const int lr = t >> 2, lg = t & 3;
#pragma unroll
        for (int rr = 0; rr < 2; rr++) {
            int row = lr + rr * 32;
            const bf16* src = base + (size_t)row * 768 + h * 32 + lg * 8;
            *(uint4*)&Ks[row][lg * 8] = *(const uint4*)(src + 256);
            *(uint4*)&Vs[row][lg * 8] = *(const uint4*)(src + 512);
        }
    }
    __syncthreads();

    const bf16* Qb = qkvQ + ((size_t)b * 64 + w * 16) * 768 + h * 32;
    uint4 aq[2];
#pragma unroll
    for (int kf = 0; kf < 2; kf++) {
        const bf16* p = Qb + kf * 16;
        aq[kf].x = *(const uint32_t*)(p + (size_t)g * 768 + 2 * tq);
        aq[kf].y = *(const uint32_t*)(p + (size_t)(g + 8) * 768 + 2 * tq);
        aq[kf].z = *(const uint32_t*)(p + (size_t)g * 768 + 2 * tq + 8);
        aq[kf].w = *(const uint32_t*)(p + (size_t)(g + 8) * 768 + 2 * tq + 8);
    }

    uint32_t k_base = smem_u32(&Ks[0][0]) +
        (uint32_t)((lane & 7) + ((lane >> 4) & 1) * 8) * RPB +
        (uint32_t)((lane >> 3) & 1) * 16;
    float s[8][4] = {};
#pragma unroll
    for (int p = 0; p < 4; p++) {
        uint32_t pa = k_base + (uint32_t)p * 16 * RPB;
#pragma unroll
        for (int kf = 0; kf < 2; kf++) {
            uint4 bp = ldsm_x4(pa + (uint32_t)kf * 32);
            mma16(s[2 * p],     aq[kf], make_uint2(bp.x, bp.y));
            mma16(s[2 * p + 1], aq[kf], make_uint2(bp.z, bp.w));
        }
    }

    const float* bb = bias + (size_t)h * 4096 + (size_t)(w * 16 + g) * 64;
    const float scale = 0.0625f;
    float slo = 0.0f, shi = 0.0f;
#pragma unroll
    for (int nf = 0; nf < 8; nf++) {
        float2 b0 = *(const float2*)(bb + nf * 8 + 2 * tq);
        float2 b1 = *(const float2*)(bb + 8 * 64 + nf * 8 + 2 * tq);
        s[nf][0] = __expf(s[nf][0] * scale + b0.x);
        s[nf][1] = __expf(s[nf][1] * scale + b0.y);
        s[nf][2] = __expf(s[nf][2] * scale + b1.x);
        s[nf][3] = __expf(s[nf][3] * scale + b1.y);
        slo += s[nf][0] + s[nf][1];
        shi += s[nf][2] + s[nf][3];
    }
    slo += __shfl_xor_sync(0xffffffffu, slo, 1);
    slo += __shfl_xor_sync(0xffffffffu, slo, 2);
    shi += __shfl_xor_sync(0xffffffffu, shi, 1);
    shi += __shfl_xor_sync(0xffffffffu, shi, 2);
    float il = 1.0f / slo, ih = 1.0f / shi;

    float o[4][4] = {};
    uint32_t vbase = smem_u32(&Vs[0][0]) + (uint32_t)(lane & 15) * RPB;
#pragma unroll
    for (int kf = 0; kf < 4; kf++) {
        uint4 ap;
        ap.x = pk(s[2 * kf][0], s[2 * kf][1]);
        ap.y = pk(s[2 * kf][2], s[2 * kf][3]);
        ap.z = pk(s[2 * kf + 1][0], s[2 * kf + 1][1]);
        ap.w = pk(s[2 * kf + 1][2], s[2 * kf + 1][3]);
        uint32_t rowaddr = vbase + (uint32_t)kf * 16 * RPB;
#pragma unroll
        for (int nf = 0; nf < 4; nf++) {
            uint2 bv = ldsm_x2_trans(rowaddr + nf * 16);
            mma16(o[nf], ap, bv);
        }
    }

    bf16* ob = out + ((size_t)b * 64 + w * 16) * 256 + h * 32;
#pragma unroll
    for (int nf = 0; nf < 4; nf++) {
        int col = nf * 8 + 2 * tq;
        *(uint32_t*)(ob + (size_t)g * 256 + col) = pk(o[nf][0] * il, o[nf][1] * il);
        *(uint32_t*)(ob + (size_t)(g + 8) * 256 + col) = pk(o[nf][2] * ih, o[nf][3] * ih);
    }
}

// ---------------------------------------------------------------------------
// launch
// ---------------------------------------------------------------------------
extern "C" void kernel_launch(void* const* d_in, const int* in_sizes, int n_in,
                              void* d_out, int out_size) {
    const float* x     = (const float*)d_in[0];
    const float* y     = (const float*)d_in[1];
    const float* Wqkv1 = (const float*)d_in[2];
    const float* bqkv1 = (const float*)d_in[3];
    const float* Wqkv2 = (const float*)d_in[4];
    const float* bqkv2 = (const float*)d_in[5];
    const float* bias1 = (const float*)d_in[6];
    const float* bias2 = (const float*)d_in[7];
    const float* Wp1   = (const float*)d_in[8];
    const float* bp1   = (const float*)d_in[9];
    const float* Wp2   = (const float*)d_in[10];
    const float* bp2   = (const float*)d_in[11];
    const float* g1    = (const float*)d_in[12];
    const float* be1   = (const float*)d_in[13];
    const float* g2    = (const float*)d_in[14];
    const float* be2   = (const float*)d_in[15];
    float* out = (float*)d_out;

    bf16 *qkv1, *qkv2, *o1, *o2, *wtq1, *wtq2, *wtp1, *wtp2;
    cudaGetSymbolAddress((void**)&qkv1, g_qkv1);
    cudaGetSymbolAddress((void**)&qkv2, g_qkv2);
    cudaGetSymbolAddress((void**)&o1, g_o1);
    cudaGetSymbolAddress((void**)&o2, g_o2);
    cudaGetSymbolAddress((void**)&wtq1, g_wtq1);
    cudaGetSymbolAddress((void**)&wtq2, g_wtq2);
    cudaGetSymbolAddress((void**)&wtp1, g_wtp1);
    cudaGetSymbolAddress((void**)&wtp2, g_wtp2);

    transpose_all<<<dim3(24, 8, 4), dim3(32, 8)>>>(Wqkv1, wtq1, Wqkv2, wtq2,
                                                   Wp1, wtp1, Wp2, wtp2);

    gemm_qkv<<<dim3(Mrows / 256, 1, 2), 512>>>(x, y, wtq1, wtq2, bqkv1, bqkv2,
                                               qkv1, qkv2);

    attn_tc<<<dim3(Bwin, Hh, 2), 128>>>(qkv1, qkv2, bias1, bias2, o1, o2);

    proj_ln<<<dim3(Mrows / 128, 1, 2), 512>>>(o1, o2, wtp1, wtp2, bp1, bp2,
                                              x, y, g1, be1, g2, be2, out);
}

// round 16
// speedup vs baseline: 1.0883x; 1.0883x over previous
#include <cuda_runtime.h>
#include <cuda_bf16.h>
#include <math.h>
#include <stdint.h>

// ---------------------------------------------------------------------------
// WindowCrossAttention  B=4096, N=64, C=256, H=8, Dh=32
// Round 16: R14 (best: A-resident 128-row gemm_qkv, R9 proj_ln) + attn with
// Q loads hoisted above the K/V staging barrier (hides Q DRAM latency).
// ---------------------------------------------------------------------------

#define Bwin 4096
#define Hh   8
#define Mrows (Bwin * 64)              // 262144

typedef __nv_bfloat16 bf16;

// scratch (static device arrays; no allocations allowed)
__device__ bf16  g_qkv1[(size_t)Mrows * 768];
__device__ bf16  g_qkv2[(size_t)Mrows * 768];
__device__ bf16  g_o1[(size_t)Mrows * 256];
__device__ bf16  g_o2[(size_t)Mrows * 256];
__device__ bf16  g_wtq1[768 * 256];
__device__ bf16  g_wtq2[768 * 256];
__device__ bf16  g_wtp1[256 * 256];
__device__ bf16  g_wtp2[256 * 256];

__device__ __forceinline__ uint32_t pk(float lo, float hi) {
    __nv_bfloat162 t = __float22bfloat162_rn(make_float2(lo, hi));
    return *reinterpret_cast<uint32_t*>(&t);
}
__device__ __forceinline__ uint32_t smem_u32(const void* p) {
    uint32_t a;
    asm("{ .reg .u64 t; cvta.to.shared.u64 t, %1; cvt.u32.u64 %0, t; }"
        : "=r"(a) : "l"(p));
    return a;
}
__device__ __forceinline__ void mma16(float* c, uint4 a, uint2 b) {
    asm volatile(
        "mma.sync.aligned.m16n8k16.row.col.f32.bf16.bf16.f32 "
        "{%0,%1,%2,%3}, {%4,%5,%6,%7}, {%8,%9}, {%0,%1,%2,%3};"
        : "+f"(c[0]), "+f"(c[1]), "+f"(c[2]), "+f"(c[3])
        : "r"(a.x), "r"(a.y), "r"(a.z), "r"(a.w), "r"(b.x), "r"(b.y));
}
__device__ __forceinline__ uint4 ldsm_x4(uint32_t addr) {
    uint4 r;
    asm volatile("ldmatrix.sync.aligned.m8n8.x4.shared.b16 {%0,%1,%2,%3}, [%4];"
                 : "=r"(r.x), "=r"(r.y), "=r"(r.z), "=r"(r.w) : "r"(addr));
    return r;
}
__device__ __forceinline__ uint2 ldsm_x2_trans(uint32_t addr) {
    uint2 r;
    asm volatile("ldmatrix.sync.aligned.m8n8.x2.trans.shared.b16 {%0,%1}, [%2];"
                 : "=r"(r.x), "=r"(r.y) : "r"(addr));
    return r;
}
__device__ __forceinline__ void cp16_cg(uint32_t dst, const void* src) {
    asm volatile("cp.async.cg.shared.global [%0], [%1], 16;"
                 :: "r"(dst), "l"(src));
}
__device__ __forceinline__ void cp_commit() {
    asm volatile("cp.async.commit_group;" ::: "memory");
}
template <int N>
__device__ __forceinline__ void cp_wait() {
    asm volatile("cp.async.wait_group %0;" :: "n"(N) : "memory");
}

// XOR swizzle for cp.async tiles: 64B rows, phys granule = g ^ ((row>>1)&3)
#define SWZ(row, g) ((uint32_t)((row) * 64 + (((g) ^ (((row) >> 1) & 3)) * 16)))

// padded-row tiles (LDG+STS path + attention): 40 bf16 = 80B rows
#define RP 40
#define RPB 80

// ---------------------------------------------------------------------------
// Weight transposes (all four in one launch, z selects)
// ---------------------------------------------------------------------------
__global__ void transpose_all(const float* __restrict__ Wq1, bf16* __restrict__ Tq1,
                              const float* __restrict__ Wq2, bf16* __restrict__ Tq2,
                              const float* __restrict__ Wp1, bf16* __restrict__ Tp1,
                              const float* __restrict__ Wp2, bf16* __restrict__ Tp2) {
    const float* W;
    bf16* Wt;
    int Nc;
    switch (blockIdx.z) {
        case 0: W = Wq1; Wt = Tq1; Nc = 768; break;
        case 1: W = Wq2; Wt = Tq2; Nc = 768; break;
        case 2: W = Wp1; Wt = Tp1; Nc = 256; break;
        default: W = Wp2; Wt = Tp2; Nc = 256; break;
    }
    if (blockIdx.x * 32 >= Nc) return;
    __shared__ float tile[32][33];
    int n0 = blockIdx.x * 32;
    int k0 = blockIdx.y * 32;
    int tx = threadIdx.x, ty = threadIdx.y;
#pragma unroll
    for (int r = 0; r < 4; r++)
        tile[ty + 8 * r][tx] = W[(size_t)(k0 + ty + 8 * r) * Nc + n0 + tx];
    __syncthreads();
#pragma unroll
    for (int r = 0; r < 4; r++)
        Wt[(size_t)(n0 + ty + 8 * r) * 256 + k0 + tx] =
            __float2bfloat16_rn(tile[tx][ty + 8 * r]);
}

// ---------------------------------------------------------------------------
// A-resident QKV GEMM (R14 exact): CTA = one 128-row m-tile, ALL 6 n-tiles.
// 256 threads, 8 warps (2m x 4n), warp 64x32 per n-tile, BK=32.
// Phase 0: A (128x256 fp32) -> bf16 smem (64KB, chunk-major).
// Mainloop: 48 B-chunks streamed via cp.async 3-stage ring. grid.z = dir.
// ---------------------------------------------------------------------------
__global__ __launch_bounds__(256, 2)
void gemm_qkv(const float* __restrict__ x, const float* __restrict__ y,
              const bf16* __restrict__ wt1, const bf16* __restrict__ wt2,
              const float* __restrict__ bq1, const float* __restrict__ bq2,
              bf16* __restrict__ c1, bf16* __restrict__ c2) {
    __shared__ __align__(16) bf16 Af[8][128][32];   // 64KB, chunk-major
    __shared__ __align__(16) bf16 Bs[3][128][32];   // 24KB
    const int Nc = 768;
    const uint32_t BBYTES = 128 * 64;

    const float* A    = blockIdx.z ? y : x;
    const bf16* Bt    = blockIdx.z ? wt2 : wt1;
    const float* bias = blockIdx.z ? bq2 : bq1;
    bf16* C           = blockIdx.z ? c2 : c1;

    const int t = threadIdx.x;
    const int w = t >> 5, lane = t & 31;
    const int warp_m = w >> 2, warp_n = w & 3;
    const int mBase = blockIdx.x * 128;

    const float* Ab = A + (size_t)mBase * 256;

    const int lr = t >> 2;          // 0..63
    const int lg = t & 3;
    const uint32_t aSm = smem_u32(&Af[0][0][0]);
    const uint32_t bSm = smem_u32(&Bs[0][0][0]);
    const uint32_t swA0 = SWZ(lr, lg);
    const uint32_t swA1 = SWZ(lr + 64, lg);

    // B chunk loader: global chunk index gi in [0,48); nt = gi>>3, c = gi&7
    auto CPB = [&](int gi) {
        int nt = gi >> 3, c = gi & 7;
        const bf16* Bb = Bt + (size_t)(nt * 128) * 256 + c * 32;
        uint32_t dst = bSm + (uint32_t)(gi % 3) * BBYTES;
#pragma unroll
        for (int rr = 0; rr < 2; rr++) {
            int row = lr + rr * 64;
            cp16_cg(dst + SWZ(row, lg), Bb + (size_t)row * 256 + lg * 8);
        }
        cp_commit();
    };

    // prefetch first two B chunks, then stage A (overlaps B DRAM fetch)
    CPB(0);
    CPB(1);
#pragma unroll 1
    for (int c = 0; c < 8; c++) {
#pragma unroll
        for (int rr = 0; rr < 2; rr++) {
            const float* p = Ab + (size_t)(lr + rr * 64) * 256 + c * 32 + lg * 8;
            float4 v0 = *(const float4*)p;
            float4 v1 = *(const float4*)(p + 4);
            uint4 pkv = { pk(v0.x, v0.y), pk(v0.z, v0.w),
                          pk(v1.x, v1.y), pk(v1.z, v1.w) };
            *(uint4*)((char*)&Af[c][0][0] + (rr ? swA1 : swA0)) = pkv;
        }
    }
    __syncthreads();   // A visible to all warps

    // ldmatrix lane addressing
    const int row0a = warp_m * 64 + (lane & 15);
    const int sela = (row0a >> 1) & 3;
    const int hia = lane >> 4;
    const uint32_t ga0 = (uint32_t)((hia ^ sela) * 16);
    const uint32_t ga1 = (uint32_t)(((2 + hia) ^ sela) * 16);
    const uint32_t aAddr = aSm + (uint32_t)row0a * 64;

    const int row0b = warp_n * 32 + (lane & 7) + ((lane >> 4) & 1) * 8;
    const int selb = (row0b >> 1) & 3;
    const int hib = (lane >> 3) & 1;
    const uint32_t gb0 = (uint32_t)((hib ^ selb) * 16);
    const uint32_t gb1 = (uint32_t)(((2 + hib) ^ selb) * 16);
    const uint32_t bAddr = bSm + (uint32_t)row0b * 64;

    const int g = lane >> 2;
    const int tq = lane & 3;

#pragma unroll 1
    for (int nt = 0; nt < 6; nt++) {
        float acc[4][4][4] = {};
#pragma unroll 1
        for (int c = 0; c < 8; c++) {
            const int gi = nt * 8 + c;
            if (gi < 47) cp_wait<1>(); else cp_wait<0>();
            __syncthreads();
            if (gi < 46) CPB(gi + 2);

            const uint32_t ab = aAddr + (uint32_t)c * 8192;
            const uint32_t bb = bAddr + (uint32_t)(gi % 3) * BBYTES;
#pragma unroll
            for (int kf = 0; kf < 2; kf++) {
                const uint32_t go_a = kf ? ga1 : ga0;
                const uint32_t go_b = kf ? gb1 : gb0;
                uint4 av[4];
#pragma unroll
                for (int mf = 0; mf < 4; mf++)
                    av[mf] = ldsm_x4(ab + (uint32_t)mf * 1024 + go_a);
                uint4 bp0 = ldsm_x4(bb + go_b);
                uint4 bp1 = ldsm_x4(bb + 1024 + go_b);
                uint2 bv[4] = { {bp0.x, bp0.y}, {bp0.z, bp0.w},
                                {bp1.x, bp1.y}, {bp1.z, bp1.w} };
#pragma unroll
                for (int mf = 0; mf < 4; mf++)
#pragma unroll
                    for (int nf = 0; nf < 4; nf++)
                        mma16(acc[mf][nf], av[mf], bv[nf]);
            }
        }

        // epilogue for this n-tile: bias add + bf16 store
        const int nBase = nt * 128;
        float2 bz[4];
#pragma unroll
        for (int nf = 0; nf < 4; nf++)
            bz[nf] = *(const float2*)(bias + nBase + warp_n * 32 + nf * 8 + 2 * tq);

#pragma unroll
        for (int mf = 0; mf < 4; mf++) {
            int row0 = mBase + warp_m * 64 + mf * 16 + g;
#pragma unroll
            for (int nf = 0; nf < 4; nf++) {
                int col = nBase + warp_n * 32 + nf * 8 + 2 * tq;
                *(uint32_t*)(C + (size_t)row0 * Nc + col) =
                    pk(acc[mf][nf][0] + bz[nf].x, acc[mf][nf][1] + bz[nf].y);
                *(uint32_t*)(C + (size_t)(row0 + 8) * Nc + col) =
                    pk(acc[mf][nf][2] + bz[nf].x, acc[mf][nf][3] + bz[nf].y);
            }
        }
    }
}

// ---------------------------------------------------------------------------
// FUSED proj + bias + residual + LayerNorm (R9 exact).  CTA 128 x 256,
// 512 threads, 16 warps (2m x 8n), BK=32, LDG+STS double buffer. grid.z = dir.
// ---------------------------------------------------------------------------
__global__ __launch_bounds__(512, 1)
void proj_ln(const bf16* __restrict__ o1, const bf16* __restrict__ o2,
             const bf16* __restrict__ wt1, const bf16* __restrict__ wt2,
             const float* __restrict__ bp1, const float* __restrict__ bp2,
             const float* __restrict__ x, const float* __restrict__ y,
             const float* __restrict__ g1, const float* __restrict__ be1,
             const float* __restrict__ g2, const float* __restrict__ be2,
             float* __restrict__ outbase) {
    __shared__ __align__(16) bf16 As[2][128][RP];   // 20KB
    __shared__ __align__(16) bf16 Bs[2][256][RP];   // 40KB
    __shared__ float2 red[128][8];                  // 8KB
    __shared__ float2 mv[128];

    const bf16* A      = blockIdx.z ? o2 : o1;
    const bf16* Bt     = blockIdx.z ? wt2 : wt1;
    const float* bias  = blockIdx.z ? bp2 : bp1;
    const float* resid = blockIdx.z ? y : x;
    const float* gamma = blockIdx.z ? g2 : g1;
    const float* beta  = blockIdx.z ? be2 : be1;
    float* out = outbase + (size_t)blockIdx.z * Mrows * 256;

    const int t = threadIdx.x;
    const int w = t >> 5, lane = t & 31;
    const int warp_m = w >> 3;        // 0..1
    const int warp_n = w & 7;         // 0..7
    const int g = lane >> 2, tq = lane & 3;
    const int mBase = blockIdx.x * 128;

    const bf16* Ab = A + (size_t)mBase * 256;

    const int lr = t >> 2;            // 0..127
    const int lg = t & 3;

    uint4 ast, bst[2];
    auto LDG = [&](int kc) {
        ast = *(const uint4*)(Ab + (size_t)lr * 256 + kc + lg * 8);
#pragma unroll
        for (int rr = 0; rr < 2; rr++)
            bst[rr] = *(const uint4*)(Bt + (size_t)(lr + rr * 128) * 256 + kc + lg * 8);
    };
    auto STS = [&](int buf) {
        *(uint4*)&As[buf][lr][lg * 8] = ast;
#pragma unroll
        for (int rr = 0; rr < 2; rr++)
            *(uint4*)&Bs[buf][lr + rr * 128][lg * 8] = bst[rr];
    };

    uint32_t a_base = smem_u32(&As[0][0][0]) +
        (uint32_t)(warp_m * 64 + (lane & 15)) * RPB + (uint32_t)(lane >> 4) * 16;
    uint32_t b_base = smem_u32(&Bs[0][0][0]) +
        (uint32_t)(warp_n * 32 + (lane & 7) + ((lane >> 4) & 1) * 8) * RPB +
        (uint32_t)((lane >> 3) & 1) * 16;

    float acc[4][4][4] = {};

    LDG(0);
    STS(0);
    __syncthreads();

#pragma unroll 1
    for (int c = 0; c < 8; c++) {
        if (c < 7) LDG((c + 1) * 32);
        const uint32_t ab = a_base + (uint32_t)(c & 1) * (128 * RPB);
        const uint32_t bb = b_base + (uint32_t)(c & 1) * (256 * RPB);
#pragma unroll
        for (int kf = 0; kf < 2; kf++) {
            uint4 av[4];
#pragma unroll
            for (int mf = 0; mf < 4; mf++)
                av[mf] = ldsm_x4(ab + (uint32_t)mf * 16 * RPB + (uint32_t)kf * 32);
            uint4 bp0 = ldsm_x4(bb + (uint32_t)kf * 32);
            uint4 bp1 = ldsm_x4(bb + 16 * RPB + (uint32_t)kf * 32);
            uint2 bv[4] = { {bp0.x, bp0.y}, {bp0.z, bp0.w},
                            {bp1.x, bp1.y}, {bp1.z, bp1.w} };
#pragma unroll
            for (int mf = 0; mf < 4; mf++)
#pragma unroll
                for (int nf = 0; nf < 4; nf++)
                    mma16(acc[mf][nf], av[mf], bv[nf]);
        }
        if (c < 7) {
            STS((c + 1) & 1);
            __syncthreads();
        }
    }

    // epilogue pass 1: val = acc + bias + resid, per-row partial stats
    float2 bz[4];
#pragma unroll
    for (int nf = 0; nf < 4; nf++)
        bz[nf] = *(const float2*)(bias + warp_n * 32 + nf * 8 + 2 * tq);

#pragma unroll
    for (int mf = 0; mf < 4; mf++) {
        int r0 = warp_m * 64 + mf * 16 + g;
        float plo = 0.0f, phi = 0.0f, qlo = 0.0f, qhi = 0.0f;
#pragma unroll
        for (int nf = 0; nf < 4; nf++) {
            int col = warp_n * 32 + nf * 8 + 2 * tq;
            float2 x0 = *(const float2*)(resid + (size_t)(mBase + r0) * 256 + col);
            float2 x1 = *(const float2*)(resid + (size_t)(mBase + r0 + 8) * 256 + col);
            float v0 = acc[mf][nf][0] + bz[nf].x + x0.x;
            float v1 = acc[mf][nf][1] + bz[nf].y + x0.y;
            float v2 = acc[mf][nf][2] + bz[nf].x + x1.x;
            float v3 = acc[mf][nf][3] + bz[nf].y + x1.y;
            acc[mf][nf][0] = v0; acc[mf][nf][1] = v1;
            acc[mf][nf][2] = v2; acc[mf][nf][3] = v3;
            plo += v0 + v1; phi += v2 + v3;
            qlo += v0 * v0 + v1 * v1; qhi += v2 * v2 + v3 * v3;
        }
        plo += __shfl_xor_sync(0xffffffffu, plo, 1);
        plo += __shfl_xor_sync(0xffffffffu, plo, 2);
        qlo += __shfl_xor_sync(0xffffffffu, qlo, 1);
        qlo += __shfl_xor_sync(0xffffffffu, qlo, 2);
        phi += __shfl_xor_sync(0xffffffffu, phi, 1);
        phi += __shfl_xor_sync(0xffffffffu, phi, 2);
        qhi += __shfl_xor_sync(0xffffffffu, qhi, 1);
        qhi += __shfl_xor_sync(0xffffffffu, qhi, 2);
        if (tq == 0) {
            red[r0][warp_n]     = make_float2(plo, qlo);
            red[r0 + 8][warp_n] = make_float2(phi, qhi);
        }
    }
    __syncthreads();

    if (t < 128) {
        float s = 0.0f, q = 0.0f;
#pragma unroll
        for (int j = 0; j < 8; j++) { s += red[t][j].x; q += red[t][j].y; }
        float mean = s * (1.0f / 256.0f);
        float var = q * (1.0f / 256.0f) - mean * mean;
        mv[t] = make_float2(mean, rsqrtf(var + 1e-5f));
    }
    __syncthreads();

    // epilogue pass 2: normalize + affine + store
#pragma unroll
    for (int nf = 0; nf < 4; nf++) {
        int col = warp_n * 32 + nf * 8 + 2 * tq;
        float2 gm = *(const float2*)(gamma + col);
        float2 bt = *(const float2*)(beta + col);
#pragma unroll
        for (int mf = 0; mf < 4; mf++) {
            int r0 = warp_m * 64 + mf * 16 + g;
            float2 m0 = mv[r0];
            float2 m1 = mv[r0 + 8];
            float2 u0 = { (acc[mf][nf][0] - m0.x) * m0.y * gm.x + bt.x,
                          (acc[mf][nf][1] - m0.x) * m0.y * gm.y + bt.y };
            float2 u1 = { (acc[mf][nf][2] - m1.x) * m1.y * gm.x + bt.x,
                          (acc[mf][nf][3] - m1.x) * m1.y * gm.y + bt.y };
            *(float2*)(out + (size_t)(mBase + r0) * 256 + col) = u0;
            *(float2*)(out + (size_t)(mBase + r0 + 8) * 256 + col) = u1;
        }
    }
}

// ---------------------------------------------------------------------------
// Tensor-core attention: block per (b,h), 128 threads (4 warps), grid.z=dir.
// Q LDGs issued BEFORE the K/V staging + barrier so their DRAM latency
// overlaps the cooperative stores (ptxas cannot hoist LDG across BAR.SYNC).
// ---------------------------------------------------------------------------
__global__ __launch_bounds__(128)
void attn_tc(const bf16* __restrict__ qkv1, const bf16* __restrict__ qkv2,
             const float* __restrict__ bias1, const float* __restrict__ bias2,
             bf16* __restrict__ o1, bf16* __restrict__ o2) {
    const bf16* qkvQ  = blockIdx.z ? qkv2 : qkv1;
    const bf16* qkvKV = blockIdx.z ? qkv1 : qkv2;
    const float* bias = blockIdx.z ? bias2 : bias1;
    bf16* out         = blockIdx.z ? o2 : o1;

    const int b = blockIdx.x;
    const int h = blockIdx.y;
    const int t = threadIdx.x;
    const int w = t >> 5;
    const int lane = t & 31;
    const int g = lane >> 2;
    const int tq = lane & 3;

    __shared__ __align__(16) bf16 Ks[64][RP];
    __shared__ __align__(16) bf16 Vs[64][RP];

    // --- Q fragment LDGs FIRST (latency overlaps K/V staging + barrier) ---
    const bf16* Qb = qkvQ + ((size_t)b * 64 + w * 16) * 768 + h * 32;
    uint4 aq[2];
#pragma unroll
    for (int kf = 0; kf < 2; kf++) {
        const bf16* p = Qb + kf * 16;
        aq[kf].x = *(const uint32_t*)(p + (size_t)g * 768 + 2 * tq);
        aq[kf].y = *(const uint32_t*)(p + (size_t)(g + 8) * 768 + 2 * tq);
        aq[kf].z = *(const uint32_t*)(p + (size_t)g * 768 + 2 * tq + 8);
        aq[kf].w = *(const uint32_t*)(p + (size_t)(g + 8) * 768 + 2 * tq + 8);
    }

    // --- cooperative K/V staging ---
    const bf16* base = qkvKV + (size_t)b * 64 * 768;
    {
        const int lr = t >> 2, lg = t & 3;
#pragma unroll
        for (int rr = 0; rr < 2; rr++) {
            int row = lr + rr * 32;
            const bf16* src = base + (size_t)row * 768 + h * 32 + lg * 8;
            *(uint4*)&Ks[row][lg * 8] = *(const uint4*)(src + 256);
            *(uint4*)&Vs[row][lg * 8] = *(const uint4*)(src + 512);
        }
    }
    __syncthreads();

    uint32_t k_base = smem_u32(&Ks[0][0]) +
        (uint32_t)((lane & 7) + ((lane >> 4) & 1) * 8) * RPB +
        (uint32_t)((lane >> 3) & 1) * 16;
    float s[8][4] = {};
#pragma unroll
    for (int p = 0; p < 4; p++) {
        uint32_t pa = k_base + (uint32_t)p * 16 * RPB;
#pragma unroll
        for (int kf = 0; kf < 2; kf++) {
            uint4 bp = ldsm_x4(pa + (uint32_t)kf * 32);
            mma16(s[2 * p],     aq[kf], make_uint2(bp.x, bp.y));
            mma16(s[2 * p + 1], aq[kf], make_uint2(bp.z, bp.w));
        }
    }

    const float* bb = bias + (size_t)h * 4096 + (size_t)(w * 16 + g) * 64;
    const float scale = 0.0625f;
    float slo = 0.0f, shi = 0.0f;
#pragma unroll
    for (int nf = 0; nf < 8; nf++) {
        float2 b0 = *(const float2*)(bb + nf * 8 + 2 * tq);
        float2 b1 = *(const float2*)(bb + 8 * 64 + nf * 8 + 2 * tq);
        s[nf][0] = __expf(s[nf][0] * scale + b0.x);
        s[nf][1] = __expf(s[nf][1] * scale + b0.y);
        s[nf][2] = __expf(s[nf][2] * scale + b1.x);
        s[nf][3] = __expf(s[nf][3] * scale + b1.y);
        slo += s[nf][0] + s[nf][1];
        shi += s[nf][2] + s[nf][3];
    }
    slo += __shfl_xor_sync(0xffffffffu, slo, 1);
    slo += __shfl_xor_sync(0xffffffffu, slo, 2);
    shi += __shfl_xor_sync(0xffffffffu, shi, 1);
    shi += __shfl_xor_sync(0xffffffffu, shi, 2);
    float il = 1.0f / slo, ih = 1.0f / shi;

    float o[4][4] = {};
    uint32_t vbase = smem_u32(&Vs[0][0]) + (uint32_t)(lane & 15) * RPB;
#pragma unroll
    for (int kf = 0; kf < 4; kf++) {
        uint4 ap;
        ap.x = pk(s[2 * kf][0], s[2 * kf][1]);
        ap.y = pk(s[2 * kf][2], s[2 * kf][3]);
        ap.z = pk(s[2 * kf + 1][0], s[2 * kf + 1][1]);
        ap.w = pk(s[2 * kf + 1][2], s[2 * kf + 1][3]);
        uint32_t rowaddr = vbase + (uint32_t)kf * 16 * RPB;
#pragma unroll
        for (int nf = 0; nf < 4; nf++) {
            uint2 bv = ldsm_x2_trans(rowaddr + nf * 16);
            mma16(o[nf], ap, bv);
        }
    }

    bf16* ob = out + ((size_t)b * 64 + w * 16) * 256 + h * 32;
#pragma unroll
    for (int nf = 0; nf < 4; nf++) {
        int col = nf * 8 + 2 * tq;
        *(uint32_t*)(ob + (size_t)g * 256 + col) = pk(o[nf][0] * il, o[nf][1] * il);
        *(uint32_t*)(ob + (size_t)(g + 8) * 256 + col) = pk(o[nf][2] * ih, o[nf][3] * ih);
    }
}

// ---------------------------------------------------------------------------
// launch
// ---------------------------------------------------------------------------
extern "C" void kernel_launch(void* const* d_in, const int* in_sizes, int n_in,
                              void* d_out, int out_size) {
    const float* x     = (const float*)d_in[0];
    const float* y     = (const float*)d_in[1];
    const float* Wqkv1 = (const float*)d_in[2];
    const float* bqkv1 = (const float*)d_in[3];
    const float* Wqkv2 = (const float*)d_in[4];
    const float* bqkv2 = (const float*)d_in[5];
    const float* bias1 = (const float*)d_in[6];
    const float* bias2 = (const float*)d_in[7];
    const float* Wp1   = (const float*)d_in[8];
    const float* bp1   = (const float*)d_in[9];
    const float* Wp2   = (const float*)d_in[10];
    const float* bp2   = (const float*)d_in[11];
    const float* g1    = (const float*)d_in[12];
    const float* be1   = (const float*)d_in[13];
    const float* g2    = (const float*)d_in[14];
    const float* be2   = (const float*)d_in[15];
    float* out = (float*)d_out;

    bf16 *qkv1, *qkv2, *o1, *o2, *wtq1, *wtq2, *wtp1, *wtp2;
    cudaGetSymbolAddress((void**)&qkv1, g_qkv1);
    cudaGetSymbolAddress((void**)&qkv2, g_qkv2);
    cudaGetSymbolAddress((void**)&o1, g_o1);
    cudaGetSymbolAddress((void**)&o2, g_o2);
    cudaGetSymbolAddress((void**)&wtq1, g_wtq1);
    cudaGetSymbolAddress((void**)&wtq2, g_wtq2);
    cudaGetSymbolAddress((void**)&wtp1, g_wtp1);
    cudaGetSymbolAddress((void**)&wtp2, g_wtp2);

    transpose_all<<<dim3(24, 8, 4), dim3(32, 8)>>>(Wqkv1, wtq1, Wqkv2, wtq2,
                                                   Wp1, wtp1, Wp2, wtp2);

    gemm_qkv<<<dim3(Mrows / 128, 1, 2), 256>>>(x, y, wtq1, wtq2, bqkv1, bqkv2,
                                               qkv1, qkv2);

    attn_tc<<<dim3(Bwin, Hh, 2), 128>>>(qkv1, qkv2, bias1, bias2, o1, o2);

    proj_ln<<<dim3(Mrows / 128, 1, 2), 512>>>(o1, o2, wtp1, wtp2, bp1, bp2,
                                              x, y, g1, be1, g2, be2, out);
}